// round 6
// baseline (speedup 1.0000x reference)
#include <cuda_runtime.h>

// GeneralMechanismODE — pure single-touch stream (96 B in, 32 B out per row).
// R6: identical body to R5 (winning structure: no loop-carried hazards,
// 4 front-batched LDG.128, 26 regs, .cs streaming hints). Block size 64:
// 32 CTAs/SM (HW max) x 64 thr = 2048 resident threads — same 64 warps/SM,
// but CTA churn granularity halved again. R5 (256->128) bought 1.8 us from
// exactly this mechanism; probing the next notch.

__global__ __launch_bounds__(64) void ode_kernel6(
    const float4* __restrict__ y,    // 2*B float4
    const float4* __restrict__ kf,   // B float4
    const float4* __restrict__ kr,   // B float4
    float4* __restrict__ out,        // 2*B float4
    int B)
{
    int b = blockIdx.x * blockDim.x + threadIdx.x;
    if (b >= B) return;

    // 4 independent 128-bit streaming loads, front-batched.
    float4 ylo = __ldcs(&y[2 * b + 0]);   // y0..y3
    float4 yhi = __ldcs(&y[2 * b + 1]);   // y4..y7
    float4 f   = __ldcs(&kf[b]);
    float4 r   = __ldcs(&kr[b]);

    float v0 = f.x * ylo.x * yhi.x - r.x * ylo.y;          // kf0*E*A  - kr0*EA
    float v1 = f.y * ylo.y * yhi.y - r.y * ylo.w;          // kf1*EA*B - kr1*EAB
    float v2 = f.z * ylo.w         - r.z * ylo.z * yhi.z;  // kf2*EAB  - kr2*EQ*P
    float v3 = f.w * ylo.z         - r.w * ylo.x * yhi.w;  // kf3*EQ   - kr3*E*Q

    float4 olo, ohi;
    olo.x = v3 - v0;   // dE
    olo.y = v0 - v1;   // dEA
    olo.z = v2 - v3;   // dEQ
    olo.w = v1 - v2;   // dEAB
    ohi.x = -v0;       // dA
    ohi.y = -v1;       // dB
    ohi.z = v2;        // dP
    ohi.w = v3;        // dQ

    __stcs(&out[2 * b + 0], olo);
    __stcs(&out[2 * b + 1], ohi);
}

extern "C" void kernel_launch(void* const* d_in, const int* in_sizes, int n_in,
                              void* d_out, int out_size)
{
    // metadata order: t (1), y (B*8), forward_rates (B*4), reverse_rates (B*4)
    const float4* y  = (const float4*)d_in[1];
    const float4* kf = (const float4*)d_in[2];
    const float4* kr = (const float4*)d_in[3];
    float4* out = (float4*)d_out;

    int B = in_sizes[1] / 8;
    int threads = 64;
    int blocks = (B + threads - 1) / threads;
    ode_kernel6<<<blocks, threads>>>(y, kf, kr, out, B);
}

// round 7
// speedup vs baseline: 1.0857x; 1.0857x over previous
#include <cuda_runtime.h>

// GeneralMechanismODE — pure single-touch stream (96 B in, 32 B out per row).
// R7: R5 config (block 128 = proven churn optimum after R6 showed block 64
// over-shoots; 26 regs; 4 front-batched LDG.128 with .cs) with ONE change:
// write-through stores (__stwt). Output must hit DRAM every graph replay
// anyway; bypassing L2 dirty allocation frees all 126 MB of L2 for the
// inbound 128 MB read stream and removes dirty-writeback turnaround.

__global__ __launch_bounds__(128) void ode_kernel7(
    const float4* __restrict__ y,    // 2*B float4
    const float4* __restrict__ kf,   // B float4
    const float4* __restrict__ kr,   // B float4
    float4* __restrict__ out,        // 2*B float4
    int B)
{
    int b = blockIdx.x * blockDim.x + threadIdx.x;
    if (b >= B) return;

    // 4 independent 128-bit streaming loads, front-batched.
    float4 ylo = __ldcs(&y[2 * b + 0]);   // y0..y3
    float4 yhi = __ldcs(&y[2 * b + 1]);   // y4..y7
    float4 f   = __ldcs(&kf[b]);
    float4 r   = __ldcs(&kr[b]);

    float v0 = f.x * ylo.x * yhi.x - r.x * ylo.y;          // kf0*E*A  - kr0*EA
    float v1 = f.y * ylo.y * yhi.y - r.y * ylo.w;          // kf1*EA*B - kr1*EAB
    float v2 = f.z * ylo.w         - r.z * ylo.z * yhi.z;  // kf2*EAB  - kr2*EQ*P
    float v3 = f.w * ylo.z         - r.w * ylo.x * yhi.w;  // kf3*EQ   - kr3*E*Q

    float4 olo, ohi;
    olo.x = v3 - v0;   // dE
    olo.y = v0 - v1;   // dEA
    olo.z = v2 - v3;   // dEQ
    olo.w = v1 - v2;   // dEAB
    ohi.x = -v0;       // dA
    ohi.y = -v1;       // dB
    ohi.z = v2;        // dP
    ohi.w = v3;        // dQ

    __stwt(&out[2 * b + 0], olo);
    __stwt(&out[2 * b + 1], ohi);
}

extern "C" void kernel_launch(void* const* d_in, const int* in_sizes, int n_in,
                              void* d_out, int out_size)
{
    // metadata order: t (1), y (B*8), forward_rates (B*4), reverse_rates (B*4)
    const float4* y  = (const float4*)d_in[1];
    const float4* kf = (const float4*)d_in[2];
    const float4* kr = (const float4*)d_in[3];
    float4* out = (float4*)d_out;

    int B = in_sizes[1] / 8;
    int threads = 128;
    int blocks = (B + threads - 1) / threads;
    ode_kernel7<<<blocks, threads>>>(y, kf, kr, out, B);
}